// round 9
// baseline (speedup 1.0000x reference)
#include <cuda_runtime.h>
#include <math.h>

#define NB   8
#define NT   500
#define NF   257
#define NC   8
#define NNUL 4
#define LOWF 5
#define HIGHF 70
#define DCF_SIZE (NB*NT*NF*NNUL)

#define OMA   0.65f
#define AOVER 0.53846156f           // a/(1-a)

#define NFG   65                    // ceil(257/4) f-groups
#define NCHUNK 4                    // t chunks of 128

typedef unsigned long long u64;

// ---------------- scratch (k_rat leaves accums zeroed for next replay) ------
__device__ float g_pre[NB*NT];
__device__ float g_aft[NB*NT*NNUL];
__device__ float g_rat[NB*NT*NNUL];

// ---------------- packed f32x2 helpers ---------------------------------------
__device__ __forceinline__ u64 pack2(float lo, float hi) {
    u64 r; asm("mov.b64 %0, {%1, %2};" : "=l"(r) : "f"(lo), "f"(hi)); return r;
}
__device__ __forceinline__ u64 dup2(float x) { return pack2(x, x); }
__device__ __forceinline__ void unpack2(u64 v, float& lo, float& hi) {
    asm("mov.b64 {%0, %1}, %2;" : "=f"(lo), "=f"(hi) : "l"(v));
}
__device__ __forceinline__ u64 fma2(u64 a, u64 b, u64 c) {
    u64 d; asm("fma.rn.f32x2 %0, %1, %2, %3;" : "=l"(d) : "l"(a), "l"(b), "l"(c)); return d;
}
__device__ __forceinline__ u64 mul2(u64 a, u64 b) {
    u64 d; asm("mul.rn.f32x2 %0, %1, %2;" : "=l"(d) : "l"(a), "l"(b)); return d;
}

// =================== k_main ===================================================
// grid = (b*4 + chunk)*65 + fgrp ; block = 128 (4 warps = 4 consecutive f)
__global__ __launch_bounds__(128)
void k_main(const float* __restrict__ in, const int* __restrict__ beam_id,
            const float* __restrict__ tw, const float* __restrict__ nw,
            float* __restrict__ out) {
    __shared__ float  xs[32][68];       // interleaved (xr,xi), e-swizzled rows
    __shared__ float2 wn2[4][NNUL][8];  // null weights, form (wr, -wi)
    __shared__ float4 q_s[4][32];
    __shared__ float2 tg_s[4][32];
    __shared__ int    fs_s[4], fv_s[4];

    int bi    = blockIdx.x;
    int fgrp  = bi % NFG;
    int rem   = bi / NFG;
    int chunk = rem & 3;
    int b     = rem >> 2;

    int tid = threadIdx.x, lane = tid & 31, w = tid >> 5;
    int f0  = fgrp * 4;
    int fv  = (f0 + w) < NF;
    int f   = min(f0 + w, NF-1);
    int beam = beam_id[b];
    bool inb = fv && (f >= LOWF) && (f < HIGHF);

    if (lane == 0) { fs_s[w] = f; fv_s[w] = fv; }

    // ---- stage null weights (once): thread -> one (f_l, n, c) float2 -------
    {
        int fl = tid >> 5, j = tid & 31, n = j >> 3, c = j & 7;
        int ff = min(f0 + fl, NF-1);
        float wr = nw[(((beam*NNUL + n)*2 + 0)*NF + ff)*NC + c];
        float wi = nw[(((beam*NNUL + n)*2 + 1)*NF + ff)*NC + c];
        wn2[fl][n][c] = make_float2(wr, -wi);
    }
    // ---- target weights -> packed regs, form (twr, -twi) -------------------
    u64 tw2[8];
    {
        const float* ar = tw + ((beam*2 + 0)*NF + f)*NC;
        const float* ai = tw + ((beam*2 + 1)*NF + f)*NC;
        float4 r0 = ((const float4*)ar)[0], r1 = ((const float4*)ar)[1];
        float4 i0 = ((const float4*)ai)[0], i1 = ((const float4*)ai)[1];
        tw2[0]=pack2(r0.x,-i0.x); tw2[1]=pack2(r0.y,-i0.y);
        tw2[2]=pack2(r0.z,-i0.z); tw2[3]=pack2(r0.w,-i0.w);
        tw2[4]=pack2(r1.x,-i1.x); tw2[5]=pack2(r1.y,-i1.y);
        tw2[6]=pack2(r1.z,-i1.z); tw2[7]=pack2(r1.w,-i1.w);
    }
    __syncthreads();

    // masked scan coefficients (per lane, once)
    const float AJ[5] = {0.35f, 0.1225f, 0.01500625f, 2.25187539e-4f, 5.07094278e-8f};
    float ajm[5]; u64 ajm2[5];
    #pragma unroll
    for (int s = 0; s < 5; s++) {
        ajm[s]  = (lane >= (1<<s)) ? AJ[s] : 0.0f;
        ajm2[s] = dup2(ajm[s]);
    }
    float pa  = exp2f((float)(lane+1) * -1.5145732f);   // a^(lane+1)
    u64   pa2 = dup2(pa);

    u64  c2[4] = {0ull,0ull,0ull,0ull};
    float c8 = 0.0f;

    const int ROWLIM = NF*NC - 4;
    int T0 = chunk * 128;
    int itstart = chunk ? -1 : 0;       // it = -1 is warmup (discard)

    for (int it = itstart; it < 4; it++) {
        int tbase = T0 + it*32;
        __syncthreads();

        // ---- stage input interleaved: task = (t_l, e); 2 passes ------------
        #pragma unroll
        for (int pass = 0; pass < 2; pass++) {
            int i  = pass*128 + tid;        // 0..255
            int tl = i >> 3, e = i & 7;
            int tg = min(tbase + tl, NT-1);
            int col = min(f0*NC + e*4, ROWLIM);
            const float* p0 = in + ((size_t)(b*NT + tg)*2 + 0)*(NF*NC) + col;
            const float* p1 = in + ((size_t)(b*NT + tg)*2 + 1)*(NF*NC) + col;
            float4 r = *(const float4*)p0;
            float4 m = *(const float4*)p1;
            int off = e*8 + ((e>>2)<<2);    // bank-clean swizzle, fits 68
            *(float4*)&xs[tl][off]   = make_float4(r.x, m.x, r.y, m.y);
            *(float4*)&xs[tl][off+4] = make_float4(r.z, m.z, r.w, m.w);
        }
        __syncthreads();

        // ---- load x pairs: phys offset = w*16 + k*4 + (w>>1)*4 -------------
        u64 x2[8], xz[8];
        #pragma unroll
        for (int k = 0; k < 4; k++) {
            float4 v = *(float4*)&xs[lane][w*16 + k*4 + ((w>>1)<<2)];
            x2[2*k]   = pack2(v.x, v.y);    // aligned pair (likely elided)
            x2[2*k+1] = pack2(v.z, v.w);
            xz[2*k]   = pack2(v.y, v.x);    // swapped
            xz[2*k+1] = pack2(v.w, v.z);
        }

        // ---- power ----
        u64 P = 0ull;
        #pragma unroll
        for (int c = 0; c < 8; c++) P = fma2(x2[c], x2[c], P);
        float plo, phi_; unpack2(P, plo, phi_);
        float u8 = OMA * ((plo + phi_) * 0.125f);

        // ---- target: A=(Σtwr xr, Σ-twi xi), B=(Σtwr xi, Σ-twi xr) ----------
        u64 A = 0ull, B = 0ull;
        #pragma unroll
        for (int c = 0; c < 8; c++) {
            A = fma2(tw2[c], x2[c], A);
            B = fma2(tw2[c], xz[c], B);
        }
        float alo, ahi, blo, bhi;
        unpack2(A, alo, ahi); unpack2(B, blo, bhi);
        float tr = alo + ahi;               // Σ twr xr - twi xi
        float ti = blo - bhi;               // Σ twr xi + twi xr

        int t  = tbase + lane;
        int tc = min(t, NT-1);

        u64 tt = pack2(OMA*tr, OMA*ti);
        u64 ts = pack2(OMA*ti, -OMA*tr);

        // ---- nulls ----
        u64 u2[4];
        #pragma unroll
        for (int n = 0; n < NNUL; n++) {
            const float4* wp = (const float4*)&wn2[w][n][0];
            u64 An = 0ull, Bn = 0ull;
            #pragma unroll
            for (int k = 0; k < 4; k++) {
                float4 wv = wp[k];          // uniform LDS.128
                u64 w0 = pack2(wv.x, wv.y);
                u64 w1 = pack2(wv.z, wv.w);
                An = fma2(w0, x2[2*k],   An);
                An = fma2(w1, x2[2*k+1], An);
                Bn = fma2(w0, xz[2*k],   Bn);
                Bn = fma2(w1, xz[2*k+1], Bn);
            }
            float nlo, nhi, mlo, mhi;
            unpack2(An, nlo, nhi); unpack2(Bn, mlo, mhi);
            float nr = nlo + nhi;
            float ni = mlo - mhi;
            // (pr,pi)*(1-a) = nr*tt + ni*ts
            u64 p2 = fma2(dup2(nr), tt, mul2(dup2(ni), ts));
            if (tc == 0)    // reference's t=0 quirk
                p2 = fma2(dup2(AOVER*ni), ts, p2);
            u2[n] = p2;
        }

        // ---- packed decayed Kogge-Stone ----
        #pragma unroll
        for (int s = 0; s < 5; s++) {
            int d = 1 << s;
            #pragma unroll
            for (int k = 0; k < 4; k++) {
                u64 v = __shfl_up_sync(0xffffffffu, u2[k], d);
                u2[k] = fma2(ajm2[s], v, u2[k]);
            }
            float vs = __shfl_up_sync(0xffffffffu, u8, d);
            u8 = fmaf(ajm[s], vs, u8);
        }
        u64 y2[4]; float y8;
        #pragma unroll
        for (int k = 0; k < 4; k++) y2[k] = fma2(pa2, c2[k], u2[k]);
        y8 = fmaf(pa, c8, u8);
        #pragma unroll
        for (int k = 0; k < 4; k++) c2[k] = __shfl_sync(0xffffffffu, y2[k], 31);
        c8 = __shfl_sync(0xffffffffu, y8, 31);

        if (it < 0) continue;           // warmup (block-uniform)

        // ---- epilogue ----
        float yr[4], yi[4];
        #pragma unroll
        for (int n = 0; n < 4; n++) unpack2(y2[n], yr[n], yi[n]);

        float rinv = __fdividef(1.0f, y8 + 1e-13f);
        float ph[4], q[4];
        #pragma unroll
        for (int n = 0; n < 4; n++) {
            ph[n] = sqrtf(fmaf(yr[n], yr[n], yi[n]*yi[n]));
            q[n]  = fminf(fmaxf(ph[n]*rinv, 0.01f), 1.0f);
        }
        if (inb && t < NT) {
            atomicAdd(g_pre + b*NT + t, y8);
            float* aftp = g_aft + (b*NT + t)*NNUL;
            #pragma unroll
            for (int n = 0; n < 4; n++) atomicAdd(aftp + n, ph[n]);
        }

        q_s[w][lane]  = make_float4(q[0], q[1], q[2], q[3]);
        tg_s[w][lane] = make_float2(tr, ti);
        __syncthreads();

        {   // dcf: thread = (t_local, fi) -> 64B contiguous runs
            int tl = tid >> 2, fi = tid & 3;
            int tt_ = tbase + tl;
            if (fv_s[fi] && tt_ < NT)
                *(float4*)(out + ((size_t)(b*NT + tt_)*NF + fs_s[fi])*4) = q_s[fi][tl];
        }
        {   // targ: thread = (part, t_local, f-pair)
            int p = tid >> 6, r2 = tid & 63, tl2 = r2 >> 1, f2 = (r2 & 1)*2;
            int tt2 = tbase + tl2;
            if (tt2 < NT) {
                size_t base = DCF_SIZE + ((size_t)(b*NT + tt2)*2 + p)*NF;
                #pragma unroll
                for (int h = 0; h < 2; h++) {
                    if (fv_s[f2+h]) {
                        float2 v = tg_s[f2+h][tl2];
                        out[base + fs_s[f2+h]] = p ? v.y : v.x;
                    }
                }
            }
        }
    }
}

// =================== k_rat: ratios + accumulator reset =======================
__global__ __launch_bounds__(256)
void k_rat(void) {
    int idx = blockIdx.x*256 + threadIdx.x;
    if (idx >= NB*NT) return;
    float pre = g_pre[idx];
    float4 af = ((const float4*)g_aft)[idx];
    float pinv = __fdividef(1.0f, pre + 1e-10f);
    float4 r;
    r.x = fminf(fmaxf(af.x*pinv, 0.01f), 1.0f);
    r.y = fminf(fmaxf(af.y*pinv, 0.01f), 1.0f);
    r.z = fminf(fmaxf(af.z*pinv, 0.01f), 1.0f);
    r.w = fminf(fmaxf(af.w*pinv, 0.01f), 1.0f);
    ((float4*)g_rat)[idx] = r;
    g_pre[idx] = 0.0f;
    ((float4*)g_aft)[idx] = make_float4(0.f, 0.f, 0.f, 0.f);
}

// =================== k_fix_flat: streaming ratio apply (t >= 1) ==============
__global__ __launch_bounds__(256)
void k_fix_flat(float* __restrict__ out) {
    int idx = blockIdx.x*256 + threadIdx.x;     // one per (b,t,f)
    if (idx >= NB*NT*NF) return;
    int bt = idx / NF;
    int t  = bt % NT;
    if (t == 0) return;
    float4 rat = ((const float4*)g_rat)[bt];
    float* p = out + (size_t)idx*4;
    float4 q = *(float4*)p;
    q.x = sqrtf(q.x * rat.x);
    q.y = sqrtf(q.y * rat.y);
    q.z = sqrtf(q.z * rat.z);
    q.w = sqrtf(q.w * rat.w);
    *(float4*)p = q;
}

// =================== launcher ===============================================
extern "C" void kernel_launch(void* const* d_in, const int* in_sizes, int n_in,
                              void* d_out, int out_size) {
    const float* in      = (const float*)d_in[0];
    const int*   beam_id = (const int*)  d_in[1];
    const float* tw      = (const float*)d_in[2];
    const float* nw      = (const float*)d_in[3];
    float* out = (float*)d_out;

    k_main<<<NB*NCHUNK*NFG, 128>>>(in, beam_id, tw, nw, out);
    k_rat<<<(NB*NT + 255)/256, 256>>>();
    k_fix_flat<<<(NB*NT*NF + 255)/256, 256>>>(out);
}

// round 10
// speedup vs baseline: 1.2164x; 1.2164x over previous
#include <cuda_runtime.h>
#include <math.h>

#define NB   8
#define NT   500
#define NF   257
#define NC   8
#define NNUL 4
#define LOWF 5
#define HIGHF 70
#define DCF_SIZE (NB*NT*NF*NNUL)

#define A_    0.35f
#define OMA   0.65f
#define AOVER 0.53846156f           // a/(1-a)

#define NFG   65                    // ceil(257/4) f-groups
#define NCHUNK 4                    // t chunks of 128 (2 iters of 64)

// ---------------- scratch (k_rat leaves accums zeroed for next replay) ------
__device__ float g_pre[NB*NT];
__device__ float g_aft[NB*NT*NNUL];
__device__ float g_rat[NB*NT*NNUL];

// =================== k_main ===================================================
// grid = (b*4 + chunk)*65 + fgrp ; block = 128 (4 warps = 4 consecutive f)
// each lane owns t-pair (tbase+2L, tbase+2L+1): 64 t per warp-iteration.
__global__ __launch_bounds__(128)
void k_main(const float* __restrict__ in, const int* __restrict__ beam_id,
            const float* __restrict__ tw, const float* __restrict__ nw,
            float* __restrict__ out) {
    __shared__ float  xs[2][32][68];   // [t parity][t/2][part*32 + f_l*8 + c]
    __shared__ float  wsm[4][80];      // [w][16 targ | 64 null]
    __shared__ float4 q_s[4][66];      // padded 66 -> conflict-free staged reads
    __shared__ float2 tg_s[4][66];
    __shared__ int    fs_s[4], fv_s[4];

    int bi    = blockIdx.x;
    int fgrp  = bi % NFG;
    int rem   = bi / NFG;
    int chunk = rem & 3;
    int b     = rem >> 2;

    int tid = threadIdx.x, lane = tid & 31, w = tid >> 5;
    int f0  = fgrp * 4;
    int fv  = (f0 + w) < NF;
    int f   = min(f0 + w, NF-1);
    int beam = beam_id[b];
    bool inb = fv && (f >= LOWF) && (f < HIGHF);

    if (lane == 0) { fs_s[w] = f; fv_s[w] = fv; }

    // ---- stage weights (once) ----
    if (lane < 16) {   // target: [part(2)][c(8)]
        int part = lane >> 3, c = lane & 7;
        wsm[w][part*8 + c] = tw[((beam*2 + part)*NF + f)*NC + c];
    }
    {   // nulls: 64 floats, 2 per lane; layout [n][ri][c]
        #pragma unroll
        for (int h = 0; h < 2; h++) {
            int j = lane + h*32;
            int n = j >> 4, ri = (j >> 3) & 1, c = j & 7;
            wsm[w][16 + j] = nw[(((beam*NNUL + n)*2 + ri)*NF + f)*NC + c];
        }
    }
    __syncthreads();

    // target weights -> registers
    float twr[8], twi[8];
    {
        float4 a0 = *(float4*)&wsm[w][0], a1 = *(float4*)&wsm[w][4];
        float4 b0 = *(float4*)&wsm[w][8], b1 = *(float4*)&wsm[w][12];
        twr[0]=a0.x; twr[1]=a0.y; twr[2]=a0.z; twr[3]=a0.w;
        twr[4]=a1.x; twr[5]=a1.y; twr[6]=a1.z; twr[7]=a1.w;
        twi[0]=b0.x; twi[1]=b0.y; twi[2]=b0.z; twi[3]=b0.w;
        twi[4]=b1.x; twi[5]=b1.y; twi[6]=b1.z; twi[7]=b1.w;
    }

    // pair-scan coefficients: AJ2[s] = (a^2)^(2^s), masked per lane
    const float AJ2[5] = {0.1225f, 0.01500625f, 2.25187539e-4f,
                          5.07094278e-8f, 2.5714352e-15f};
    float ajm[5];
    #pragma unroll
    for (int s = 0; s < 5; s++) ajm[s] = (lane >= (1<<s)) ? AJ2[s] : 0.0f;
    float pa2 = exp2f((float)(lane+1) * -3.0291464f);   // (a^2)^(lane+1)

    float cR[9];
    #pragma unroll
    for (int k = 0; k < 9; k++) cR[k] = 0.0f;

    const int ROWLIM = NF*NC - 4;
    int T0 = chunk * 128;
    int itstart = chunk ? -1 : 0;       // it = -1: warmup 64 t (discard)

    for (int it = itstart; it < 2; it++) {
        int tbase = T0 + it*64;

        // ---- stage input: 64 t x 2 parts x 32 floats = 1024 float4 tasks ---
        #pragma unroll
        for (int pass = 0; pass < 8; pass++) {
            int i   = pass*128 + tid;       // 0..1023
            int seg = i >> 3;               // 0..127 = tl*2 + part
            int tl  = seg >> 1, part = seg & 1, e = i & 7;
            int tg  = min(tbase + tl, NT-1);
            int col = min(f0*NC + e*4, ROWLIM);
            const float* p = in + ((size_t)(b*NT + tg)*2 + part)*(NF*NC) + col;
            *(float4*)&xs[tl & 1][tl >> 1][part*32 + e*4] = *(const float4*)p;
        }
        __syncthreads();

        int ta = tbase + 2*lane;
        int tb = ta + 1;
        int tca = min(ta, NT-1);

        // ---- load x for both t ----
        float xra[8], xia[8], xrb[8], xib[8];
        {
            float4 r0 = *(float4*)&xs[0][lane][w*8];
            float4 r1 = *(float4*)&xs[0][lane][w*8 + 4];
            float4 i0 = *(float4*)&xs[0][lane][32 + w*8];
            float4 i1 = *(float4*)&xs[0][lane][32 + w*8 + 4];
            xra[0]=r0.x; xra[1]=r0.y; xra[2]=r0.z; xra[3]=r0.w;
            xra[4]=r1.x; xra[5]=r1.y; xra[6]=r1.z; xra[7]=r1.w;
            xia[0]=i0.x; xia[1]=i0.y; xia[2]=i0.z; xia[3]=i0.w;
            xia[4]=i1.x; xia[5]=i1.y; xia[6]=i1.z; xia[7]=i1.w;
        }
        {
            float4 r0 = *(float4*)&xs[1][lane][w*8];
            float4 r1 = *(float4*)&xs[1][lane][w*8 + 4];
            float4 i0 = *(float4*)&xs[1][lane][32 + w*8];
            float4 i1 = *(float4*)&xs[1][lane][32 + w*8 + 4];
            xrb[0]=r0.x; xrb[1]=r0.y; xrb[2]=r0.z; xrb[3]=r0.w;
            xrb[4]=r1.x; xrb[5]=r1.y; xrb[6]=r1.z; xrb[7]=r1.w;
            xib[0]=i0.x; xib[1]=i0.y; xib[2]=i0.z; xib[3]=i0.w;
            xib[4]=i1.x; xib[5]=i1.y; xib[6]=i1.z; xib[7]=i1.w;
        }

        // ---- target + power for both t ----
        float tra=0.f, tia=0.f, trb=0.f, tib=0.f, pwa=0.f, pwb=0.f;
        #pragma unroll
        for (int c = 0; c < 8; c++) {
            tra = fmaf(twr[c], xra[c], tra); tra = fmaf(-twi[c], xia[c], tra);
            tia = fmaf(twi[c], xra[c], tia); tia = fmaf( twr[c], xia[c], tia);
            trb = fmaf(twr[c], xrb[c], trb); trb = fmaf(-twi[c], xib[c], trb);
            tib = fmaf(twi[c], xrb[c], tib); tib = fmaf( twr[c], xib[c], tib);
            pwa = fmaf(xra[c], xra[c], pwa); pwa = fmaf(xia[c], xia[c], pwa);
            pwb = fmaf(xrb[c], xrb[c], pwb); pwb = fmaf(xib[c], xib[c], pwb);
        }

        float ua[9], ub[9];
        ua[8] = pwa * (0.125f*OMA);
        ub[8] = pwb * (0.125f*OMA);

        // ---- nulls: weights loaded once, used for both t ----
        #pragma unroll
        for (int n = 0; n < NNUL; n++) {
            float nwr_[8], nwi_[8];
            {
                float4 c0 = *(float4*)&wsm[w][16 + n*16];
                float4 c1 = *(float4*)&wsm[w][16 + n*16 + 4];
                float4 d0 = *(float4*)&wsm[w][16 + n*16 + 8];
                float4 d1 = *(float4*)&wsm[w][16 + n*16 + 12];
                nwr_[0]=c0.x; nwr_[1]=c0.y; nwr_[2]=c0.z; nwr_[3]=c0.w;
                nwr_[4]=c1.x; nwr_[5]=c1.y; nwr_[6]=c1.z; nwr_[7]=c1.w;
                nwi_[0]=d0.x; nwi_[1]=d0.y; nwi_[2]=d0.z; nwi_[3]=d0.w;
                nwi_[4]=d1.x; nwi_[5]=d1.y; nwi_[6]=d1.z; nwi_[7]=d1.w;
            }
            float nra=0.f, nia=0.f, nrb=0.f, nib=0.f;
            #pragma unroll
            for (int c = 0; c < 8; c++) {
                nra = fmaf(nwr_[c], xra[c], nra); nra = fmaf(-nwi_[c], xia[c], nra);
                nia = fmaf(nwi_[c], xra[c], nia); nia = fmaf( nwr_[c], xia[c], nia);
                nrb = fmaf(nwr_[c], xrb[c], nrb); nrb = fmaf(-nwi_[c], xib[c], nrb);
                nib = fmaf(nwi_[c], xrb[c], nib); nib = fmaf( nwr_[c], xib[c], nib);
            }
            float pra = tra*nra + tia*nia;
            float pia = tia*nra - tra*nia;
            if (tca == 0) {   // reference's t=0 quirk (chunk0, it0, lane0)
                pra = fmaf( AOVER*tia, nia, pra);
                pia = fmaf(-AOVER*tra, nia, pia);
            }
            ua[n]   = OMA*pra;
            ua[4+n] = OMA*pia;
            float prb = trb*nrb + tib*nib;
            float pib = tib*nrb - trb*nib;
            ub[n]   = OMA*prb;
            ub[4+n] = OMA*pib;
        }

        // ---- pair-combined decayed Kogge-Stone (64 t per warp-iter) --------
        // v = u_b + a*u_a ; scan v with a^2 coeffs -> y_b ; y_a = u_a + a*y_b[-1]
        float ya[9], yb[9];
        #pragma unroll
        for (int k = 0; k < 9; k++) {
            float v = fmaf(A_, ua[k], ub[k]);
            #pragma unroll
            for (int s = 0; s < 5; s++) {
                float sv = __shfl_up_sync(0xffffffffu, v, 1<<s);
                v = fmaf(ajm[s], sv, v);
            }
            float ybk = fmaf(pa2, cR[k], v);
            float ybp = __shfl_up_sync(0xffffffffu, ybk, 1);
            if (lane == 0) ybp = cR[k];
            ya[k] = fmaf(A_, ybp, ua[k]);
            yb[k] = ybk;
            cR[k] = __shfl_sync(0xffffffffu, ybk, 31);
        }

        if (it >= 0) {
            // ---- epilogue for both t: pre-ratio q, band atomics -------------
            float rinva = __fdividef(1.0f, ya[8] + 1e-13f);
            float rinvb = __fdividef(1.0f, yb[8] + 1e-13f);
            float pha[4], qa[4], phb[4], qb[4];
            #pragma unroll
            for (int n = 0; n < 4; n++) {
                pha[n] = sqrtf(fmaf(ya[n], ya[n], ya[4+n]*ya[4+n]));
                qa[n]  = fminf(fmaxf(pha[n]*rinva, 0.01f), 1.0f);
                phb[n] = sqrtf(fmaf(yb[n], yb[n], yb[4+n]*yb[4+n]));
                qb[n]  = fminf(fmaxf(phb[n]*rinvb, 0.01f), 1.0f);
            }
            if (inb) {
                if (ta < NT) {
                    atomicAdd(g_pre + b*NT + ta, ya[8]);
                    float* aftp = g_aft + (b*NT + ta)*NNUL;
                    #pragma unroll
                    for (int n = 0; n < 4; n++) atomicAdd(aftp + n, pha[n]);
                }
                if (tb < NT) {
                    atomicAdd(g_pre + b*NT + tb, yb[8]);
                    float* aftp = g_aft + (b*NT + tb)*NNUL;
                    #pragma unroll
                    for (int n = 0; n < 4; n++) atomicAdd(aftp + n, phb[n]);
                }
            }
            q_s[w][2*lane]    = make_float4(qa[0], qa[1], qa[2], qa[3]);
            q_s[w][2*lane+1]  = make_float4(qb[0], qb[1], qb[2], qb[3]);
            tg_s[w][2*lane]   = make_float2(tra, tia);
            tg_s[w][2*lane+1] = make_float2(trb, tib);
        }
        __syncthreads();

        if (it >= 0) {
            // dcf: task = (t_local 64, fi 4) -> 2 passes
            #pragma unroll
            for (int pass = 0; pass < 2; pass++) {
                int task = pass*128 + tid;
                int fi = task & 3, tl = task >> 2;
                int tt = tbase + tl;
                if (fv_s[fi] && tt < NT)
                    *(float4*)(out + ((size_t)(b*NT + tt)*NF + fs_s[fi])*4) = q_s[fi][tl];
            }
            // targ: task = (p, t_local, fi) -> 4 passes
            #pragma unroll
            for (int pass = 0; pass < 4; pass++) {
                int j = pass*128 + tid;          // 0..511
                int p = j >> 8, rm = j & 255, tl = rm >> 2, fi = rm & 3;
                int tt = tbase + tl;
                if (fv_s[fi] && tt < NT) {
                    float2 v = tg_s[fi][tl];
                    out[DCF_SIZE + ((size_t)(b*NT + tt)*2 + p)*NF + fs_s[fi]] =
                        p ? v.y : v.x;
                }
            }
        }
        __syncthreads();   // xs/q_s safe for next iteration's writers
    }
}

// =================== k_rat: ratios + accumulator reset =======================
__global__ __launch_bounds__(256)
void k_rat(void) {
    int idx = blockIdx.x*256 + threadIdx.x;
    if (idx >= NB*NT) return;
    float pre = g_pre[idx];
    float4 af = ((const float4*)g_aft)[idx];
    float pinv = __fdividef(1.0f, pre + 1e-10f);
    float4 r;
    r.x = fminf(fmaxf(af.x*pinv, 0.01f), 1.0f);
    r.y = fminf(fmaxf(af.y*pinv, 0.01f), 1.0f);
    r.z = fminf(fmaxf(af.z*pinv, 0.01f), 1.0f);
    r.w = fminf(fmaxf(af.w*pinv, 0.01f), 1.0f);
    ((float4*)g_rat)[idx] = r;
    g_pre[idx] = 0.0f;
    ((float4*)g_aft)[idx] = make_float4(0.f, 0.f, 0.f, 0.f);
}

// =================== k_fix_flat: streaming ratio apply (t >= 1) ==============
__global__ __launch_bounds__(256)
void k_fix_flat(float* __restrict__ out) {
    int idx = blockIdx.x*256 + threadIdx.x;     // one per (b,t,f)
    if (idx >= NB*NT*NF) return;
    int bt = idx / NF;
    int t  = bt % NT;
    if (t == 0) return;
    float4 rat = ((const float4*)g_rat)[bt];
    float* p = out + (size_t)idx*4;
    float4 q = *(float4*)p;
    q.x = sqrtf(q.x * rat.x);
    q.y = sqrtf(q.y * rat.y);
    q.z = sqrtf(q.z * rat.z);
    q.w = sqrtf(q.w * rat.w);
    *(float4*)p = q;
}

// =================== launcher ===============================================
extern "C" void kernel_launch(void* const* d_in, const int* in_sizes, int n_in,
                              void* d_out, int out_size) {
    const float* in      = (const float*)d_in[0];
    const int*   beam_id = (const int*)  d_in[1];
    const float* tw      = (const float*)d_in[2];
    const float* nw      = (const float*)d_in[3];
    float* out = (float*)d_out;

    k_main<<<NB*NCHUNK*NFG, 128>>>(in, beam_id, tw, nw, out);
    k_rat<<<(NB*NT + 255)/256, 256>>>();
    k_fix_flat<<<(NB*NT*NF + 255)/256, 256>>>(out);
}

// round 11
// speedup vs baseline: 1.5084x; 1.2400x over previous
#include <cuda_runtime.h>
#include <math.h>

#define NB   8
#define NT   500
#define NF   257
#define NC   8
#define NNUL 4
#define LOWF 5
#define HIGHF 70
#define DCF_SIZE (NB*NT*NF*NNUL)

#define OMA   0.65f
#define AOVER 0.53846156f           // a/(1-a)

#define NFG   65                    // ceil(257/4) f-groups
#define NCHUNK 4                    // t chunks of 128

// ---------------- scratch (k_rat leaves accums zeroed for next replay) ------
__device__ float g_pre[NB*NT];
__device__ float g_aft[NB*NT*NNUL];
__device__ float g_rat[NB*NT*NNUL];

// ---------------- decayed Kogge-Stone over 32 lanes --------------------------
__device__ __forceinline__ void scan9(float u[9], int lane) {
    const float AJ0=0.35f, AJ1=0.1225f, AJ2=0.01500625f,
                AJ3=2.25187539e-4f, AJ4=5.07094278e-8f;
    #pragma unroll
    for (int kk = 0; kk < 9; kk++) {
        float v;
        v = __shfl_up_sync(0xffffffffu, u[kk], 1);  if (lane>=1)  u[kk]=fmaf(AJ0,v,u[kk]);
        v = __shfl_up_sync(0xffffffffu, u[kk], 2);  if (lane>=2)  u[kk]=fmaf(AJ1,v,u[kk]);
        v = __shfl_up_sync(0xffffffffu, u[kk], 4);  if (lane>=4)  u[kk]=fmaf(AJ2,v,u[kk]);
        v = __shfl_up_sync(0xffffffffu, u[kk], 8);  if (lane>=8)  u[kk]=fmaf(AJ3,v,u[kk]);
        v = __shfl_up_sync(0xffffffffu, u[kk], 16); if (lane>=16) u[kk]=fmaf(AJ4,v,u[kk]);
    }
}

// =================== k_main: R8 design + software-pipelined staging ==========
// grid = (b*4 + chunk)*65 + fgrp ; block = 128 (4 warps = 4 consecutive f)
__global__ __launch_bounds__(128)
void k_main(const float* __restrict__ in, const int* __restrict__ beam_id,
            const float* __restrict__ tw, const float* __restrict__ nw,
            float* __restrict__ out) {
    __shared__ float  xs[32][68];     // staged input: [t_local][part*32 + (f_l*8+c)]
    __shared__ float  wsm[4][80];     // per-warp weights: [w][16 targ | 64 null]
    __shared__ float4 q_s[4][32];
    __shared__ float2 tg_s[4][32];
    __shared__ int    fs_s[4], fv_s[4];

    int bi    = blockIdx.x;
    int fgrp  = bi % NFG;
    int rem   = bi / NFG;
    int chunk = rem & 3;
    int b     = rem >> 2;

    int tid = threadIdx.x, lane = tid & 31, w = tid >> 5;
    int f0  = fgrp * 4;
    int fv  = (f0 + w) < NF;
    int f   = min(f0 + w, NF-1);
    int beam = beam_id[b];
    bool inb = fv && (f >= LOWF) && (f < HIGHF);

    if (lane == 0) { fs_s[w] = f; fv_s[w] = fv; }

    // ---- stage weights (once) ----
    if (lane < 16) {
        int part = lane >> 3, c = lane & 7;
        wsm[w][part*8 + c] = tw[((beam*2 + part)*NF + f)*NC + c];
    }
    {
        #pragma unroll
        for (int h = 0; h < 2; h++) {
            int j = lane + h*32;
            int n = j >> 4, ri = (j >> 3) & 1, c = j & 7;
            wsm[w][16 + j] = nw[(((beam*NNUL + n)*2 + ri)*NF + f)*NC + c];
        }
    }
    __syncthreads();

    // target weights -> registers
    float twr[8], twi[8];
    {
        float4 a0 = *(float4*)&wsm[w][0], a1 = *(float4*)&wsm[w][4];
        float4 b0 = *(float4*)&wsm[w][8], b1 = *(float4*)&wsm[w][12];
        twr[0]=a0.x; twr[1]=a0.y; twr[2]=a0.z; twr[3]=a0.w;
        twr[4]=a1.x; twr[5]=a1.y; twr[6]=a1.z; twr[7]=a1.w;
        twi[0]=b0.x; twi[1]=b0.y; twi[2]=b0.z; twi[3]=b0.w;
        twi[4]=b1.x; twi[5]=b1.y; twi[6]=b1.z; twi[7]=b1.w;
    }

    float pa = exp2f((float)(lane+1) * -1.5145732f);   // a^(lane+1)
    float carry[9];
    #pragma unroll
    for (int k = 0; k < 9; k++) carry[k] = 0.0f;

    // ---- per-pass staging constants (4 float4 tasks per thread) ----
    const int ROWLIM = NF*NC - 4;
    int tl_[4], off_[4];
    const float* pbase_[4];
    {
        const float* inb0 = in + (size_t)b*NT*2*(NF*NC);
        #pragma unroll
        for (int pass = 0; pass < 4; pass++) {
            int i   = pass*128 + tid;       // 0..511
            int seg = i >> 3;
            int tl  = seg >> 1, part = seg & 1, e = i & 7;
            int col = min(f0*NC + e*4, ROWLIM);
            tl_[pass]    = tl;
            off_[pass]   = part*32 + e*4;
            pbase_[pass] = inb0 + (size_t)part*(NF*NC) + col;
        }
    }

    int T0 = chunk * 128;
    int itstart = chunk ? -1 : 0;       // it = -1 is warmup (discard)

    // ---- prefetch first iteration ----
    float4 pf[4];
    {
        int tbase = T0 + itstart*32;
        #pragma unroll
        for (int pass = 0; pass < 4; pass++) {
            int tg = min(tbase + tl_[pass], NT-1);
            pf[pass] = *(const float4*)(pbase_[pass] + (size_t)tg*2*(NF*NC));
        }
    }

    for (int it = itstart; it < 4; it++) {
        int tbase = T0 + it*32;

        // ---- commit prefetched input to smem ----
        #pragma unroll
        for (int pass = 0; pass < 4; pass++)
            *(float4*)&xs[tl_[pass]][off_[pass]] = pf[pass];
        __syncthreads();

        // ---- prefetch next iteration (overlaps with compute below) ----
        if (it < 3) {
            int tnext = tbase + 32;
            #pragma unroll
            for (int pass = 0; pass < 4; pass++) {
                int tg = min(tnext + tl_[pass], NT-1);
                pf[pass] = *(const float4*)(pbase_[pass] + (size_t)tg*2*(NF*NC));
            }
        }

        // ---- beamform from smem ----
        float xr[8], xi[8];
        {
            float4 r0 = *(float4*)&xs[lane][w*8];
            float4 r1 = *(float4*)&xs[lane][w*8 + 4];
            float4 i0 = *(float4*)&xs[lane][32 + w*8];
            float4 i1 = *(float4*)&xs[lane][32 + w*8 + 4];
            xr[0]=r0.x; xr[1]=r0.y; xr[2]=r0.z; xr[3]=r0.w;
            xr[4]=r1.x; xr[5]=r1.y; xr[6]=r1.z; xr[7]=r1.w;
            xi[0]=i0.x; xi[1]=i0.y; xi[2]=i0.z; xi[3]=i0.w;
            xi[4]=i1.x; xi[5]=i1.y; xi[6]=i1.z; xi[7]=i1.w;
        }

        float tr=0.f, ti=0.f, pw=0.f;
        #pragma unroll
        for (int c = 0; c < 8; c++) {
            tr = fmaf(twr[c], xr[c], tr); tr = fmaf(-twi[c], xi[c], tr);
            ti = fmaf(twi[c], xr[c], ti); ti = fmaf( twr[c], xi[c], ti);
            pw = fmaf(xr[c], xr[c], pw);  pw = fmaf(xi[c], xi[c], pw);
        }
        pw *= 0.125f;

        int t  = tbase + lane;
        int tc = min(t, NT-1);
        float u[9];
        #pragma unroll
        for (int n = 0; n < NNUL; n++) {
            float nwr_[8], nwi_[8];
            {
                float4 c0 = *(float4*)&wsm[w][16 + n*16];
                float4 c1 = *(float4*)&wsm[w][16 + n*16 + 4];
                float4 d0 = *(float4*)&wsm[w][16 + n*16 + 8];
                float4 d1 = *(float4*)&wsm[w][16 + n*16 + 12];
                nwr_[0]=c0.x; nwr_[1]=c0.y; nwr_[2]=c0.z; nwr_[3]=c0.w;
                nwr_[4]=c1.x; nwr_[5]=c1.y; nwr_[6]=c1.z; nwr_[7]=c1.w;
                nwi_[0]=d0.x; nwi_[1]=d0.y; nwi_[2]=d0.z; nwi_[3]=d0.w;
                nwi_[4]=d1.x; nwi_[5]=d1.y; nwi_[6]=d1.z; nwi_[7]=d1.w;
            }
            float nr=0.f, ni=0.f;
            #pragma unroll
            for (int c = 0; c < 8; c++) {
                nr = fmaf(nwr_[c], xr[c], nr); nr = fmaf(-nwi_[c], xi[c], nr);
                ni = fmaf(nwi_[c], xr[c], ni); ni = fmaf( nwr_[c], xi[c], ni);
            }
            float pr = tr*nr + ti*ni;
            float pi = ti*nr - tr*ni;
            if (tc == 0) {   // reference's t=0 quirk (chunk 0, iter 0, lane 0)
                pr = fmaf( AOVER*ti, ni, pr);
                pi = fmaf(-AOVER*tr, ni, pi);
            }
            u[n]   = OMA*pr;
            u[4+n] = OMA*pi;
        }
        u[8] = OMA*pw;

        scan9(u, lane);
        float y[9];
        #pragma unroll
        for (int k = 0; k < 9; k++) y[k] = fmaf(pa, carry[k], u[k]);
        #pragma unroll
        for (int k = 0; k < 9; k++) carry[k] = __shfl_sync(0xffffffffu, y[k], 31);

        if (it < 0) { __syncthreads(); continue; }   // warmup: fence xs reads

        // ---- epilogue: pre-ratio q, band atomics, staged coalesced stores --
        float rinv = __fdividef(1.0f, y[8] + 1e-13f);
        float ph[4], q[4];
        #pragma unroll
        for (int n = 0; n < 4; n++) {
            ph[n] = sqrtf(fmaf(y[n], y[n], y[4+n]*y[4+n]));
            q[n]  = fminf(fmaxf(ph[n]*rinv, 0.01f), 1.0f);
        }
        if (inb && t < NT) {
            atomicAdd(g_pre + b*NT + t, y[8]);
            float* aftp = g_aft + (b*NT + t)*NNUL;
            #pragma unroll
            for (int n = 0; n < 4; n++) atomicAdd(aftp + n, ph[n]);
        }

        q_s[w][lane]  = make_float4(q[0], q[1], q[2], q[3]);
        tg_s[w][lane] = make_float2(tr, ti);
        __syncthreads();   // fences q_s writes AND xs reads (next STS safe)

        {   // dcf: thread = (t_local, fi) -> 64B contiguous runs
            int tl = tid >> 2, fi = tid & 3;
            int tt = tbase + tl;
            if (fv_s[fi] && tt < NT)
                *(float4*)(out + ((size_t)(b*NT + tt)*NF + fs_s[fi])*4) = q_s[fi][tl];
        }
        {   // targ: thread = (part, t_local, f-pair)
            int p = tid >> 6, r2 = tid & 63, tl2 = r2 >> 1, f2 = (r2 & 1)*2;
            int tt2 = tbase + tl2;
            if (tt2 < NT) {
                size_t base = DCF_SIZE + ((size_t)(b*NT + tt2)*2 + p)*NF;
                #pragma unroll
                for (int h = 0; h < 2; h++) {
                    if (fv_s[f2+h]) {
                        float2 v = tg_s[f2+h][tl2];
                        out[base + fs_s[f2+h]] = p ? v.y : v.x;
                    }
                }
            }
        }
        // no trailing sync needed: next iter's STS->sync fences q_s/tg_s reads
    }
}

// =================== k_rat: ratios + accumulator reset =======================
__global__ __launch_bounds__(256)
void k_rat(void) {
    int idx = blockIdx.x*256 + threadIdx.x;
    if (idx >= NB*NT) return;
    float pre = g_pre[idx];
    float4 af = ((const float4*)g_aft)[idx];
    float pinv = __fdividef(1.0f, pre + 1e-10f);
    float4 r;
    r.x = fminf(fmaxf(af.x*pinv, 0.01f), 1.0f);
    r.y = fminf(fmaxf(af.y*pinv, 0.01f), 1.0f);
    r.z = fminf(fmaxf(af.z*pinv, 0.01f), 1.0f);
    r.w = fminf(fmaxf(af.w*pinv, 0.01f), 1.0f);
    ((float4*)g_rat)[idx] = r;
    g_pre[idx] = 0.0f;
    ((float4*)g_aft)[idx] = make_float4(0.f, 0.f, 0.f, 0.f);
}

// =================== k_fix_flat: streaming ratio apply (t >= 1) ==============
__global__ __launch_bounds__(256)
void k_fix_flat(float* __restrict__ out) {
    int idx = blockIdx.x*256 + threadIdx.x;     // one per (b,t,f)
    if (idx >= NB*NT*NF) return;
    int bt = idx / NF;
    int t  = bt % NT;
    if (t == 0) return;
    float4 rat = ((const float4*)g_rat)[bt];
    float* p = out + (size_t)idx*4;
    float4 q = *(float4*)p;
    q.x = sqrtf(q.x * rat.x);
    q.y = sqrtf(q.y * rat.y);
    q.z = sqrtf(q.z * rat.z);
    q.w = sqrtf(q.w * rat.w);
    *(float4*)p = q;
}

// =================== launcher ===============================================
extern "C" void kernel_launch(void* const* d_in, const int* in_sizes, int n_in,
                              void* d_out, int out_size) {
    const float* in      = (const float*)d_in[0];
    const int*   beam_id = (const int*)  d_in[1];
    const float* tw      = (const float*)d_in[2];
    const float* nw      = (const float*)d_in[3];
    float* out = (float*)d_out;

    k_main<<<NB*NCHUNK*NFG, 128>>>(in, beam_id, tw, nw, out);
    k_rat<<<(NB*NT + 255)/256, 256>>>();
    k_fix_flat<<<(NB*NT*NF + 255)/256, 256>>>(out);
}

// round 12
// speedup vs baseline: 1.5712x; 1.0417x over previous
#include <cuda_runtime.h>
#include <math.h>
#include <stdint.h>

#define NB   8
#define NT   500
#define NF   257
#define NC   8
#define NNUL 4
#define LOWF 5
#define HIGHF 70
#define DCF_SIZE (NB*NT*NF*NNUL)

#define OMA   0.65f
#define AOVER 0.53846156f           // a/(1-a)

#define NFG   65                    // ceil(257/4) f-groups
#define NCHUNK 4                    // t chunks of 128

#define ROWF  (NF*NC)               // 2056 floats per (bt,part) row
#define XSBUF (32*68)               // floats per xs buffer

// ---------------- scratch (k_rat leaves accums zeroed for next replay) ------
__device__ float g_pre[NB*NT];
__device__ float g_aft[NB*NT*NNUL];
__device__ float g_rat[NB*NT*NNUL];

// ---------------- cp.async helpers -------------------------------------------
__device__ __forceinline__ void cp16(uint32_t dst, const float* src) {
    asm volatile("cp.async.cg.shared.global [%0], [%1], 16;" :: "r"(dst), "l"(src));
}
__device__ __forceinline__ void cp_commit() {
    asm volatile("cp.async.commit_group;");
}

// ---------------- decayed Kogge-Stone over 32 lanes --------------------------
__device__ __forceinline__ void scan9(float u[9], int lane) {
    const float AJ0=0.35f, AJ1=0.1225f, AJ2=0.01500625f,
                AJ3=2.25187539e-4f, AJ4=5.07094278e-8f;
    #pragma unroll
    for (int kk = 0; kk < 9; kk++) {
        float v;
        v = __shfl_up_sync(0xffffffffu, u[kk], 1);  if (lane>=1)  u[kk]=fmaf(AJ0,v,u[kk]);
        v = __shfl_up_sync(0xffffffffu, u[kk], 2);  if (lane>=2)  u[kk]=fmaf(AJ1,v,u[kk]);
        v = __shfl_up_sync(0xffffffffu, u[kk], 4);  if (lane>=4)  u[kk]=fmaf(AJ2,v,u[kk]);
        v = __shfl_up_sync(0xffffffffu, u[kk], 8);  if (lane>=8)  u[kk]=fmaf(AJ3,v,u[kk]);
        v = __shfl_up_sync(0xffffffffu, u[kk], 16); if (lane>=16) u[kk]=fmaf(AJ4,v,u[kk]);
    }
}

// =================== k_main: R8 design + cp.async double-buffered staging ====
// grid = (b*4 + chunk)*65 + fgrp ; block = 128 (4 warps = 4 consecutive f)
__global__ __launch_bounds__(128, 5)
void k_main(const float* __restrict__ in, const int* __restrict__ beam_id,
            const float* __restrict__ tw, const float* __restrict__ nw,
            float* __restrict__ out) {
    __shared__ __align__(16) float xs[2][32][68];  // double-buffered staging
    __shared__ float  wsm[4][80];     // per-warp weights: [w][16 targ | 64 null]
    __shared__ float4 q_s[4][32];
    __shared__ float2 tg_s[4][32];
    __shared__ int    fs_s[4], fv_s[4];

    int bi    = blockIdx.x;
    int fgrp  = bi % NFG;
    int rem   = bi / NFG;
    int chunk = rem & 3;
    int b     = rem >> 2;

    int tid = threadIdx.x, lane = tid & 31, w = tid >> 5;
    int f0  = fgrp * 4;
    int fv  = (f0 + w) < NF;
    int f   = min(f0 + w, NF-1);
    int beam = beam_id[b];
    bool inb = fv && (f >= LOWF) && (f < HIGHF);

    if (lane == 0) { fs_s[w] = f; fv_s[w] = fv; }

    // ---- stage weights (once) ----
    if (lane < 16) {
        int part = lane >> 3, c = lane & 7;
        wsm[w][part*8 + c] = tw[((beam*2 + part)*NF + f)*NC + c];
    }
    {
        #pragma unroll
        for (int h = 0; h < 2; h++) {
            int j = lane + h*32;
            int n = j >> 4, ri = (j >> 3) & 1, c = j & 7;
            wsm[w][16 + j] = nw[(((beam*NNUL + n)*2 + ri)*NF + f)*NC + c];
        }
    }
    __syncthreads();

    // target weights -> registers
    float twr[8], twi[8];
    {
        float4 a0 = *(float4*)&wsm[w][0], a1 = *(float4*)&wsm[w][4];
        float4 b0 = *(float4*)&wsm[w][8], b1 = *(float4*)&wsm[w][12];
        twr[0]=a0.x; twr[1]=a0.y; twr[2]=a0.z; twr[3]=a0.w;
        twr[4]=a1.x; twr[5]=a1.y; twr[6]=a1.z; twr[7]=a1.w;
        twi[0]=b0.x; twi[1]=b0.y; twi[2]=b0.z; twi[3]=b0.w;
        twi[4]=b1.x; twi[5]=b1.y; twi[6]=b1.z; twi[7]=b1.w;
    }

    float pa = exp2f((float)(lane+1) * -1.5145732f);   // a^(lane+1)
    float carry[9];
    #pragma unroll
    for (int k = 0; k < 9; k++) carry[k] = 0.0f;

    // ---- per-pass staging constants (4 cp.async tasks per thread) ----
    const int ROWLIM = ROWF - 4;
    int tl_[4];
    uint32_t dst_[4];
    const float* pbase_[4];
    {
        uint32_t xs0 = (uint32_t)__cvta_generic_to_shared(&xs[0][0][0]);
        const float* inb0 = in + (size_t)b*NT*2*ROWF;
        #pragma unroll
        for (int pass = 0; pass < 4; pass++) {
            int i   = pass*128 + tid;       // 0..511
            int seg = i >> 3;
            int tl  = seg >> 1, part = seg & 1, e = i & 7;
            int col = min(f0*NC + e*4, ROWLIM);
            tl_[pass]    = tl;
            dst_[pass]   = xs0 + (uint32_t)(tl*68 + part*32 + e*4)*4;
            pbase_[pass] = inb0 + (size_t)part*ROWF + col;
        }
    }

    int T0 = chunk * 128;
    int itstart = chunk ? -1 : 0;       // it = -1 is warmup (discard)

    // ---- prologue: stage first iteration into buf (itstart & 1) ----
    {
        int tbase = T0 + itstart*32;
        uint32_t bofs = (uint32_t)(itstart & 1) * (XSBUF*4);
        #pragma unroll
        for (int pass = 0; pass < 4; pass++) {
            int tg = min(tbase + tl_[pass], NT-1);
            cp16(dst_[pass] + bofs, pbase_[pass] + (size_t)tg*2*ROWF);
        }
        cp_commit();
    }

    for (int it = itstart; it < 4; it++) {
        int tbase = T0 + it*32;
        int buf   = it & 1;             // (-1)&1 == 1: consistent with prologue

        // ---- issue next iteration's group (overlaps current compute) ----
        if (it < 3) {
            int tnext = tbase + 32;
            uint32_t bofs = (uint32_t)((it+1) & 1) * (XSBUF*4);
            #pragma unroll
            for (int pass = 0; pass < 4; pass++) {
                int tg = min(tnext + tl_[pass], NT-1);
                cp16(dst_[pass] + bofs, pbase_[pass] + (size_t)tg*2*ROWF);
            }
            cp_commit();
            asm volatile("cp.async.wait_group 1;");
        } else {
            asm volatile("cp.async.wait_group 0;");
        }
        __syncthreads();                // current buffer fully staged, visible

        // ---- beamform from smem ----
        float xr[8], xi[8];
        {
            float4 r0 = *(float4*)&xs[buf][lane][w*8];
            float4 r1 = *(float4*)&xs[buf][lane][w*8 + 4];
            float4 i0 = *(float4*)&xs[buf][lane][32 + w*8];
            float4 i1 = *(float4*)&xs[buf][lane][32 + w*8 + 4];
            xr[0]=r0.x; xr[1]=r0.y; xr[2]=r0.z; xr[3]=r0.w;
            xr[4]=r1.x; xr[5]=r1.y; xr[6]=r1.z; xr[7]=r1.w;
            xi[0]=i0.x; xi[1]=i0.y; xi[2]=i0.z; xi[3]=i0.w;
            xi[4]=i1.x; xi[5]=i1.y; xi[6]=i1.z; xi[7]=i1.w;
        }

        float tr=0.f, ti=0.f, pw=0.f;
        #pragma unroll
        for (int c = 0; c < 8; c++) {
            tr = fmaf(twr[c], xr[c], tr); tr = fmaf(-twi[c], xi[c], tr);
            ti = fmaf(twi[c], xr[c], ti); ti = fmaf( twr[c], xi[c], ti);
            pw = fmaf(xr[c], xr[c], pw);  pw = fmaf(xi[c], xi[c], pw);
        }
        pw *= 0.125f;

        int t  = tbase + lane;
        int tc = min(t, NT-1);
        float u[9];
        #pragma unroll
        for (int n = 0; n < NNUL; n++) {
            float nwr_[8], nwi_[8];
            {
                float4 c0 = *(float4*)&wsm[w][16 + n*16];
                float4 c1 = *(float4*)&wsm[w][16 + n*16 + 4];
                float4 d0 = *(float4*)&wsm[w][16 + n*16 + 8];
                float4 d1 = *(float4*)&wsm[w][16 + n*16 + 12];
                nwr_[0]=c0.x; nwr_[1]=c0.y; nwr_[2]=c0.z; nwr_[3]=c0.w;
                nwr_[4]=c1.x; nwr_[5]=c1.y; nwr_[6]=c1.z; nwr_[7]=c1.w;
                nwi_[0]=d0.x; nwi_[1]=d0.y; nwi_[2]=d0.z; nwi_[3]=d0.w;
                nwi_[4]=d1.x; nwi_[5]=d1.y; nwi_[6]=d1.z; nwi_[7]=d1.w;
            }
            float nr=0.f, ni=0.f;
            #pragma unroll
            for (int c = 0; c < 8; c++) {
                nr = fmaf(nwr_[c], xr[c], nr); nr = fmaf(-nwi_[c], xi[c], nr);
                ni = fmaf(nwi_[c], xr[c], ni); ni = fmaf( nwr_[c], xi[c], ni);
            }
            float pr = tr*nr + ti*ni;
            float pi = ti*nr - tr*ni;
            if (tc == 0) {   // reference's t=0 quirk (chunk 0, iter 0, lane 0)
                pr = fmaf( AOVER*ti, ni, pr);
                pi = fmaf(-AOVER*tr, ni, pi);
            }
            u[n]   = OMA*pr;
            u[4+n] = OMA*pi;
        }
        u[8] = OMA*pw;

        scan9(u, lane);
        float y[9];
        #pragma unroll
        for (int k = 0; k < 9; k++) y[k] = fmaf(pa, carry[k], u[k]);
        #pragma unroll
        for (int k = 0; k < 9; k++) carry[k] = __shfl_sync(0xffffffffu, y[k], 31);

        if (it < 0) continue;           // warmup: discard (xs buffers disjoint)

        // ---- epilogue: pre-ratio q, band atomics, staged coalesced stores --
        float rinv = __fdividef(1.0f, y[8] + 1e-13f);
        float ph[4], q[4];
        #pragma unroll
        for (int n = 0; n < 4; n++) {
            ph[n] = sqrtf(fmaf(y[n], y[n], y[4+n]*y[4+n]));
            q[n]  = fminf(fmaxf(ph[n]*rinv, 0.01f), 1.0f);
        }
        if (inb && t < NT) {
            atomicAdd(g_pre + b*NT + t, y[8]);
            float* aftp = g_aft + (b*NT + t)*NNUL;
            #pragma unroll
            for (int n = 0; n < 4; n++) atomicAdd(aftp + n, ph[n]);
        }

        q_s[w][lane]  = make_float4(q[0], q[1], q[2], q[3]);
        tg_s[w][lane] = make_float2(tr, ti);
        __syncthreads();                // q_s/tg_s writes visible to readers

        {   // dcf: thread = (t_local, fi) -> 64B contiguous runs
            int tl = tid >> 2, fi = tid & 3;
            int tt = tbase + tl;
            if (fv_s[fi] && tt < NT)
                *(float4*)(out + ((size_t)(b*NT + tt)*NF + fs_s[fi])*4) = q_s[fi][tl];
        }
        {   // targ: thread = (part, t_local, f-pair)
            int p = tid >> 6, r2 = tid & 63, tl2 = r2 >> 1, f2 = (r2 & 1)*2;
            int tt2 = tbase + tl2;
            if (tt2 < NT) {
                size_t base = DCF_SIZE + ((size_t)(b*NT + tt2)*2 + p)*NF;
                #pragma unroll
                for (int h = 0; h < 2; h++) {
                    if (fv_s[f2+h]) {
                        float2 v = tg_s[f2+h][tl2];
                        out[base + fs_s[f2+h]] = p ? v.y : v.x;
                    }
                }
            }
        }
        // q_s reads are fenced by next iteration's wait+syncthreads.
    }
}

// =================== k_rat: ratios + accumulator reset =======================
__global__ __launch_bounds__(256)
void k_rat(void) {
    int idx = blockIdx.x*256 + threadIdx.x;
    if (idx >= NB*NT) return;
    float pre = g_pre[idx];
    float4 af = ((const float4*)g_aft)[idx];
    float pinv = __fdividef(1.0f, pre + 1e-10f);
    float4 r;
    r.x = fminf(fmaxf(af.x*pinv, 0.01f), 1.0f);
    r.y = fminf(fmaxf(af.y*pinv, 0.01f), 1.0f);
    r.z = fminf(fmaxf(af.z*pinv, 0.01f), 1.0f);
    r.w = fminf(fmaxf(af.w*pinv, 0.01f), 1.0f);
    ((float4*)g_rat)[idx] = r;
    g_pre[idx] = 0.0f;
    ((float4*)g_aft)[idx] = make_float4(0.f, 0.f, 0.f, 0.f);
}

// =================== k_fix_flat: streaming ratio apply (t >= 1) ==============
__global__ __launch_bounds__(256)
void k_fix_flat(float* __restrict__ out) {
    int idx = blockIdx.x*256 + threadIdx.x;     // one per (b,t,f)
    if (idx >= NB*NT*NF) return;
    int bt = idx / NF;
    int t  = bt % NT;
    if (t == 0) return;
    float4 rat = ((const float4*)g_rat)[bt];
    float* p = out + (size_t)idx*4;
    float4 q = *(float4*)p;
    q.x = sqrtf(q.x * rat.x);
    q.y = sqrtf(q.y * rat.y);
    q.z = sqrtf(q.z * rat.z);
    q.w = sqrtf(q.w * rat.w);
    *(float4*)p = q;
}

// =================== launcher ===============================================
extern "C" void kernel_launch(void* const* d_in, const int* in_sizes, int n_in,
                              void* d_out, int out_size) {
    const float* in      = (const float*)d_in[0];
    const int*   beam_id = (const int*)  d_in[1];
    const float* tw      = (const float*)d_in[2];
    const float* nw      = (const float*)d_in[3];
    float* out = (float*)d_out;

    k_main<<<NB*NCHUNK*NFG, 128>>>(in, beam_id, tw, nw, out);
    k_rat<<<(NB*NT + 255)/256, 256>>>();
    k_fix_flat<<<(NB*NT*NF + 255)/256, 256>>>(out);
}